// round 1
// baseline (speedup 1.0000x reference)
#include <cuda_runtime.h>
#include <math.h>
#include <stdint.h>

#define KC 4
#define D  8

// ln(2*pi)
#define LOG_2PI 1.8378770664093453

// Precomputed per-component parameters + class masks, filled on device by
// setup_kernel (everything is data-dependent on `indices`, so no host logic).
struct Params {
    float Linv[KC][D][D];   // inverse Cholesky factor (lower triangular), row-major
    float bias[KC][D];      // b[r] = sum_c Linv[r][c] * mu[c]   (so sol = Linv*x - b)
    float cfix[KC];         // 0.5*D*log(2pi) - half_log_det
    int   active[KC];       // class i participates (indices[i] != 0)
    int   tmask[KC];        // one-hot bit of target component ci = indices[i]
    int   wmask[KC];        // bit j set if indices[j] != ci (included in total_ll)
    int   cnt;              // number of active classes
    int   _pad;
};

__device__ Params g_p;
__device__ double g_sum;

// ---------------------------------------------------------------------------
// Kernel 1: tiny setup — Cholesky (fp64), triangular inverse, log-det, masks.
// ---------------------------------------------------------------------------
__global__ void setup_kernel(const float* __restrict__ means,
                             const float* __restrict__ covs,
                             const int*   __restrict__ indices)
{
    if (threadIdx.x != 0 || blockIdx.x != 0) return;
    g_sum = 0.0;

    double L[D][D], Li[D][D];
    for (int j = 0; j < KC; ++j) {
        const float* a = covs + j * D * D;
        // Cholesky: cov = L * L^T
        for (int r = 0; r < D; ++r) {
            for (int c = 0; c <= r; ++c) {
                double s = (double)a[r * D + c];
                for (int k = 0; k < c; ++k) s -= L[r][k] * L[c][k];
                L[r][c] = (c == r) ? sqrt(s) : s / L[c][c];
            }
        }
        // Invert lower-triangular L, accumulate half-log-det
        double hld = 0.0;
        for (int c = 0; c < D; ++c) {
            Li[c][c] = 1.0 / L[c][c];
            for (int r = c + 1; r < D; ++r) {
                double s = 0.0;
                for (int k = c; k < r; ++k) s += L[r][k] * Li[k][c];
                Li[r][c] = -s / L[r][r];
            }
            hld += log(L[c][c]);
        }
        for (int r = 0; r < D; ++r)
            for (int c = 0; c < D; ++c)
                g_p.Linv[j][r][c] = (c <= r) ? (float)Li[r][c] : 0.0f;
        // bias[r] = sum_c Li[r][c] * mu[c]
        for (int r = 0; r < D; ++r) {
            double s = 0.0;
            for (int c = 0; c <= r; ++c) s += Li[r][c] * (double)means[j * D + c];
            g_p.bias[j][r] = (float)s;
        }
        g_p.cfix[j] = (float)(0.5 * (double)D * LOG_2PI - hld);
    }

    int cnt = 0;
    for (int i = 0; i < KC; ++i) {
        int ci = indices[i];
        int act = (ci != 0);
        g_p.active[i] = act;
        if (act) cnt++;
        int ti = ci; if (ti < 0) ti = 0; if (ti > KC - 1) ti = KC - 1;
        g_p.tmask[i] = 1 << ti;
        int wm = 0;
        for (int jj = 0; jj < KC; ++jj)
            if (indices[jj] != ci) wm |= (1 << jj);
        g_p.wmask[i] = wm;
    }
    g_p.cnt = cnt;
}

// ---------------------------------------------------------------------------
// Kernel 2: hot path. Each thread processes 4 consecutive samples (float4
// loads over the d-strided layout) for every active class; fp32 math like the
// reference; fp64 tree reduction + one double atomicAdd per block.
// ---------------------------------------------------------------------------
__global__ void __launch_bounds__(256) lp_kernel(const float* __restrict__ pred, int N)
{
    __shared__ Params sp;
    {
        const int nw = (int)(sizeof(Params) / 4);
        const int* src = (const int*)&g_p;
        int* dst = (int*)&sp;
        for (int u = threadIdx.x; u < nw; u += blockDim.x) dst[u] = src[u];
    }
    __syncthreads();

    const int N4 = N >> 2;
    const int tid = blockIdx.x * blockDim.x + threadIdx.x;
    const int stride = gridDim.x * blockDim.x;

    float acc = 0.0f;

    for (int v = tid; v < N4; v += stride) {
        #pragma unroll
        for (int i = 0; i < KC; ++i) {
            if (!sp.active[i]) continue;
            const float4* base = (const float4*)pred + (size_t)i * D * N4;
            float4 x[D];
            #pragma unroll
            for (int dd = 0; dd < D; ++dd)
                x[dd] = base[(size_t)dd * N4 + v];

            float lp[KC][4];
            #pragma unroll
            for (int j = 0; j < KC; ++j) {
                float M0 = 0.f, M1 = 0.f, M2 = 0.f, M3 = 0.f;
                #pragma unroll
                for (int r = 0; r < D; ++r) {
                    float nb = -sp.bias[j][r];
                    float s0 = nb, s1 = nb, s2 = nb, s3 = nb;
                    #pragma unroll
                    for (int c = 0; c <= r; ++c) {
                        float l = sp.Linv[j][r][c];
                        s0 = fmaf(l, x[c].x, s0);
                        s1 = fmaf(l, x[c].y, s1);
                        s2 = fmaf(l, x[c].z, s2);
                        s3 = fmaf(l, x[c].w, s3);
                    }
                    M0 = fmaf(s0, s0, M0);
                    M1 = fmaf(s1, s1, M1);
                    M2 = fmaf(s2, s2, M2);
                    M3 = fmaf(s3, s3, M3);
                }
                float cf = sp.cfix[j];
                lp[j][0] = fmaf(0.5f, M0, cf);
                lp[j][1] = fmaf(0.5f, M1, cf);
                lp[j][2] = fmaf(0.5f, M2, cf);
                lp[j][3] = fmaf(0.5f, M3, cf);
            }

            const int tm = sp.tmask[i];
            const int wm = sp.wmask[i];
            #pragma unroll
            for (int s = 0; s < 4; ++s) {
                float e0 = expf(lp[0][s]);
                float e1 = expf(lp[1][s]);
                float e2 = expf(lp[2][s]);
                float e3 = expf(lp[3][s]);
                float tot = 1e-8f;
                tot += (wm & 1) ? e0 : 0.0f;
                tot += (wm & 2) ? e1 : 0.0f;
                tot += (wm & 4) ? e2 : 0.0f;
                tot += (wm & 8) ? e3 : 0.0f;
                float tll = (tm & 1) ? lp[0][s]
                          : (tm & 2) ? lp[1][s]
                          : (tm & 4) ? lp[2][s] : lp[3][s];
                float et  = (tm & 1) ? e0
                          : (tm & 2) ? e1
                          : (tm & 4) ? e2 : e3;
                acc += tll - logf(tot + et);
            }
        }
    }

    // fp64 block reduction
    double dacc = (double)acc;
    #pragma unroll
    for (int off = 16; off > 0; off >>= 1)
        dacc += __shfl_down_sync(0xffffffffu, dacc, off);
    __shared__ double wsum[8];
    int lane = threadIdx.x & 31;
    int w = threadIdx.x >> 5;
    if (lane == 0) wsum[w] = dacc;
    __syncthreads();
    if (w == 0) {
        int nwarp = blockDim.x >> 5;
        double b = (lane < nwarp) ? wsum[lane] : 0.0;
        #pragma unroll
        for (int off = 4; off > 0; off >>= 1)
            b += __shfl_down_sync(0xffffffffu, b, off);
        if (lane == 0) atomicAdd(&g_sum, b);
    }
}

// ---------------------------------------------------------------------------
// Kernel 3: tail samples (N%4) + finalize scalar output.
// ---------------------------------------------------------------------------
__global__ void final_kernel(const float* __restrict__ pred, int N,
                             float* __restrict__ out)
{
    if (threadIdx.x != 0 || blockIdx.x != 0) return;
    double s = g_sum;
    const int n0 = (N >> 2) << 2;
    for (int n = n0; n < N; ++n) {
        for (int i = 0; i < KC; ++i) {
            if (!g_p.active[i]) continue;
            const float* base = pred + (size_t)i * D * N;
            float lp[KC];
            for (int j = 0; j < KC; ++j) {
                float M = 0.f;
                for (int r = 0; r < D; ++r) {
                    float sr = -g_p.bias[j][r];
                    for (int c = 0; c <= r; ++c)
                        sr = fmaf(g_p.Linv[j][r][c], base[(size_t)c * N + n], sr);
                    M = fmaf(sr, sr, M);
                }
                lp[j] = fmaf(0.5f, M, g_p.cfix[j]);
            }
            int tm = g_p.tmask[i], wm = g_p.wmask[i];
            float tot = 1e-8f, tll = 0.f, et = 0.f;
            for (int j = 0; j < KC; ++j) {
                if ((wm >> j) & 1) tot += expf(lp[j]);
                if ((tm >> j) & 1) { tll = lp[j]; et = expf(lp[j]); }
            }
            s += (double)(tll - logf(tot + et));
        }
    }
    int cnt = g_p.cnt;
    float res = 0.0f;
    if (cnt > 0 && N > 0)
        res = (float)(-s / ((double)N * (double)cnt));
    out[0] = res;
}

// ---------------------------------------------------------------------------
extern "C" void kernel_launch(void* const* d_in, const int* in_sizes, int n_in,
                              void* d_out, int out_size)
{
    const float* pred    = (const float*)d_in[0];  // (K, d, N)
    const float* means   = (const float*)d_in[1];  // (K, d)
    const float* covs    = (const float*)d_in[2];  // (K, d, d)
    const int*   indices = (const int*)d_in[3];    // (K,)

    const int N = in_sizes[0] / (KC * D);

    setup_kernel<<<1, 32>>>(means, covs, indices);

    const int N4 = N >> 2;
    const int threads = 256;
    int blocks = (N4 + threads - 1) / threads;
    if (blocks < 1) blocks = 1;
    lp_kernel<<<blocks, threads>>>(pred, N);

    final_kernel<<<1, 32>>>(pred, N, (float*)d_out);
}

// round 3
// speedup vs baseline: 1.8559x; 1.8559x over previous
#include <cuda_runtime.h>
#include <math.h>
#include <stdint.h>

#define KC 4
#define D  8

// ln(2*pi)
#define LOG_2PI 1.8378770664093453f

// Precomputed per-component parameters + class masks, filled on device by
// setup_kernel (everything is data-dependent on `indices`, so no host logic).
struct Params {
    float Linv[KC][D][D];   // inverse Cholesky factor (lower triangular), row-major
    float bias[KC][D];      // b[r] = sum_c Linv[r][c] * mu[c]   (so sol = Linv*x - b)
    float cfix[KC];         // 0.5*D*log(2pi) - half_log_det
    int   active[KC];       // class i participates (indices[i] != 0)
    int   tmask[KC];        // one-hot bit of target component ci = indices[i]
    int   wmask[KC];        // bit j set if indices[j] != ci (included in total_ll)
    int   cnt;              // number of active classes
    int   _pad;
};

__device__ Params g_p;
__device__ double g_sum;

// ---------------------------------------------------------------------------
// Kernel 1: setup — fp32 Cholesky/inverse/log-det, ONE THREAD PER COMPONENT
// (round-1 ncu: the single-thread fp64 version was 62.6us of serial DFMA
// latency; fp32 lat=4 + 4-way parallelism collapses the chain).
// ---------------------------------------------------------------------------
__global__ void setup_kernel(const float* __restrict__ means,
                             const float* __restrict__ covs,
                             const int*   __restrict__ indices)
{
    const int j = threadIdx.x;
    if (blockIdx.x != 0 || j >= KC) return;

    float L[D][D], Li[D][D];
    {
        const float* a = covs + j * D * D;
        // Cholesky: cov = L * L^T
        #pragma unroll
        for (int r = 0; r < D; ++r) {
            #pragma unroll
            for (int c = 0; c <= r; ++c) {
                float s = a[r * D + c];
                for (int k = 0; k < c; ++k) s -= L[r][k] * L[c][k];
                L[r][c] = (c == r) ? sqrtf(s) : s / L[c][c];
            }
        }
        // Invert lower-triangular L, accumulate half-log-det
        float hld = 0.0f;
        #pragma unroll
        for (int c = 0; c < D; ++c) {
            Li[c][c] = 1.0f / L[c][c];
            for (int r = c + 1; r < D; ++r) {
                float s = 0.0f;
                for (int k = c; k < r; ++k) s += L[r][k] * Li[k][c];
                Li[r][c] = -s / L[r][r];
            }
            hld += logf(L[c][c]);
        }
        #pragma unroll
        for (int r = 0; r < D; ++r)
            #pragma unroll
            for (int c = 0; c < D; ++c)
                g_p.Linv[j][r][c] = (c <= r) ? Li[r][c] : 0.0f;
        // bias[r] = sum_c Li[r][c] * mu[c]
        #pragma unroll
        for (int r = 0; r < D; ++r) {
            float s = 0.0f;
            for (int c = 0; c <= r; ++c) s += Li[r][c] * means[j * D + c];
            g_p.bias[j][r] = s;
        }
        g_p.cfix[j] = 0.5f * (float)D * LOG_2PI - hld;
    }

    if (j == 0) {
        g_sum = 0.0;
        int cnt = 0;
        for (int i = 0; i < KC; ++i) {
            int ci = indices[i];
            int act = (ci != 0);
            g_p.active[i] = act;
            if (act) cnt++;
            int ti = ci; if (ti < 0) ti = 0; if (ti > KC - 1) ti = KC - 1;
            g_p.tmask[i] = 1 << ti;
            int wm = 0;
            for (int jj = 0; jj < KC; ++jj)
                if (indices[jj] != ci) wm |= (1 << jj);
            g_p.wmask[i] = wm;
        }
        g_p.cnt = cnt;
    }
}

// ---------------------------------------------------------------------------
// Kernel 2: hot path. Each thread processes 4 consecutive samples (float4
// loads over the d-strided layout) for every active class; fp32 math with
// MUFU-path __expf/__logf; fp64 tree reduction + one double atomic per block.
// ---------------------------------------------------------------------------
__global__ void __launch_bounds__(256) lp_kernel(const float* __restrict__ pred, int N)
{
    __shared__ Params sp;
    {
        const int nw = (int)(sizeof(Params) / 4);
        const int* src = (const int*)&g_p;
        int* dst = (int*)&sp;
        for (int u = threadIdx.x; u < nw; u += blockDim.x) dst[u] = src[u];
    }
    __syncthreads();

    const int N4 = N >> 2;
    const int tid = blockIdx.x * blockDim.x + threadIdx.x;
    const int stride = gridDim.x * blockDim.x;

    float acc = 0.0f;

    for (int v = tid; v < N4; v += stride) {
        #pragma unroll
        for (int i = 0; i < KC; ++i) {
            if (!sp.active[i]) continue;
            const float4* base = (const float4*)pred + (size_t)i * D * N4;
            float4 x[D];
            #pragma unroll
            for (int dd = 0; dd < D; ++dd)
                x[dd] = base[(size_t)dd * N4 + v];

            float lp[KC][4];
            #pragma unroll
            for (int j = 0; j < KC; ++j) {
                float M0 = 0.f, M1 = 0.f, M2 = 0.f, M3 = 0.f;
                #pragma unroll
                for (int r = 0; r < D; ++r) {
                    float nb = -sp.bias[j][r];
                    float s0 = nb, s1 = nb, s2 = nb, s3 = nb;
                    #pragma unroll
                    for (int c = 0; c <= r; ++c) {
                        float l = sp.Linv[j][r][c];
                        s0 = fmaf(l, x[c].x, s0);
                        s1 = fmaf(l, x[c].y, s1);
                        s2 = fmaf(l, x[c].z, s2);
                        s3 = fmaf(l, x[c].w, s3);
                    }
                    M0 = fmaf(s0, s0, M0);
                    M1 = fmaf(s1, s1, M1);
                    M2 = fmaf(s2, s2, M2);
                    M3 = fmaf(s3, s3, M3);
                }
                float cf = sp.cfix[j];
                lp[j][0] = fmaf(0.5f, M0, cf);
                lp[j][1] = fmaf(0.5f, M1, cf);
                lp[j][2] = fmaf(0.5f, M2, cf);
                lp[j][3] = fmaf(0.5f, M3, cf);
            }

            const int tm = sp.tmask[i];
            const int wm = sp.wmask[i];
            #pragma unroll
            for (int s = 0; s < 4; ++s) {
                float e0 = __expf(lp[0][s]);
                float e1 = __expf(lp[1][s]);
                float e2 = __expf(lp[2][s]);
                float e3 = __expf(lp[3][s]);
                float tot = 1e-8f;
                tot += (wm & 1) ? e0 : 0.0f;
                tot += (wm & 2) ? e1 : 0.0f;
                tot += (wm & 4) ? e2 : 0.0f;
                tot += (wm & 8) ? e3 : 0.0f;
                float tll = (tm & 1) ? lp[0][s]
                          : (tm & 2) ? lp[1][s]
                          : (tm & 4) ? lp[2][s] : lp[3][s];
                float et  = (tm & 1) ? e0
                          : (tm & 2) ? e1
                          : (tm & 4) ? e2 : e3;
                acc += tll - __logf(tot + et);
            }
        }
    }

    // fp64 block reduction
    double dacc = (double)acc;
    #pragma unroll
    for (int off = 16; off > 0; off >>= 1)
        dacc += __shfl_down_sync(0xffffffffu, dacc, off);
    __shared__ double wsum[8];
    int lane = threadIdx.x & 31;
    int w = threadIdx.x >> 5;
    if (lane == 0) wsum[w] = dacc;
    __syncthreads();
    if (w == 0) {
        int nwarp = blockDim.x >> 5;
        double b = (lane < nwarp) ? wsum[lane] : 0.0;
        #pragma unroll
        for (int off = 4; off > 0; off >>= 1)
            b += __shfl_down_sync(0xffffffffu, b, off);
        if (lane == 0) atomicAdd(&g_sum, b);
    }
}

// ---------------------------------------------------------------------------
// Kernel 3: tail samples (N%4) + finalize scalar output.
// ---------------------------------------------------------------------------
__global__ void final_kernel(const float* __restrict__ pred, int N,
                             float* __restrict__ out)
{
    if (threadIdx.x != 0 || blockIdx.x != 0) return;
    double s = g_sum;
    const int n0 = (N >> 2) << 2;
    for (int n = n0; n < N; ++n) {
        for (int i = 0; i < KC; ++i) {
            if (!g_p.active[i]) continue;
            const float* base = pred + (size_t)i * D * N;
            float lp[KC];
            for (int j = 0; j < KC; ++j) {
                float M = 0.f;
                for (int r = 0; r < D; ++r) {
                    float sr = -g_p.bias[j][r];
                    for (int c = 0; c <= r; ++c)
                        sr = fmaf(g_p.Linv[j][r][c], base[(size_t)c * N + n], sr);
                    M = fmaf(sr, sr, M);
                }
                lp[j] = fmaf(0.5f, M, g_p.cfix[j]);
            }
            int tm = g_p.tmask[i], wm = g_p.wmask[i];
            float tot = 1e-8f, tll = 0.f, et = 0.f;
            for (int j = 0; j < KC; ++j) {
                if ((wm >> j) & 1) tot += __expf(lp[j]);
                if ((tm >> j) & 1) { tll = lp[j]; et = __expf(lp[j]); }
            }
            s += (double)(tll - __logf(tot + et));
        }
    }
    int cnt = g_p.cnt;
    float res = 0.0f;
    if (cnt > 0 && N > 0)
        res = (float)(-s / ((double)N * (double)cnt));
    out[0] = res;
}

// ---------------------------------------------------------------------------
extern "C" void kernel_launch(void* const* d_in, const int* in_sizes, int n_in,
                              void* d_out, int out_size)
{
    const float* pred    = (const float*)d_in[0];  // (K, d, N)
    const float* means   = (const float*)d_in[1];  // (K, d)
    const float* covs    = (const float*)d_in[2];  // (K, d, d)
    const int*   indices = (const int*)d_in[3];    // (K,)

    const int N = in_sizes[0] / (KC * D);

    setup_kernel<<<1, 32>>>(means, covs, indices);

    const int N4 = N >> 2;
    const int threads = 256;
    int blocks = (N4 + threads - 1) / threads;
    if (blocks < 1) blocks = 1;
    lp_kernel<<<blocks, threads>>>(pred, N);

    final_kernel<<<1, 32>>>(pred, N, (float*)d_out);
}